// round 2
// baseline (speedup 1.0000x reference)
#include <cuda_runtime.h>
#include <math.h>

// Problem constants
#define BD 2
#define TT 2048
#define CC 2048
#define NH 16
#define HD 128
#define MTOT (BD * TT)   // 4096 rows of x

// Scratch (device globals: allocation-free rule)
__device__ float g_q[BD * NH * TT * HD];   // [B,H,T,D]
__device__ float g_k[BD * NH * TT * HD];
__device__ float g_v[BD * NH * TT * HD];
__device__ float g_y[BD * TT * CC];        // attention output, [B,T,C]

// ---------------------------------------------------------------------------
// SGEMM: out = A[M,K] * W[N,K]^T   (both row-major over K, "NT" form)
// BM=BN=128, BK=16, 256 threads, 8x8 per-thread microtile.
// MODE 0: QKV — blockIdx.z selects W/out, epilogue permutes to [B,H,T,D].
// MODE 1: final projection — A is g_y, W is w_o, plain [M,N] output.
// ---------------------------------------------------------------------------
#define GBM 128
#define GBN 128
#define GBK 16
#define GAS 132   // padded smem stride (2-way store conflicts only)

template <int MODE>
__global__ __launch_bounds__(256)
void sgemm_nt(const float* __restrict__ A,
              const float* __restrict__ W0,
              const float* __restrict__ W1,
              const float* __restrict__ W2,
              float* __restrict__ Oplain)
{
    const int K = CC;
    const float* Aptr;
    const float* W;
    float* outq = nullptr;
    if (MODE == 0) {
        Aptr = A;
        W    = (blockIdx.z == 0) ? W0 : (blockIdx.z == 1) ? W1 : W2;
        outq = (blockIdx.z == 0) ? g_q : (blockIdx.z == 1) ? g_k : g_v;
    } else {
        Aptr = g_y;
        W    = W0;
    }

    __shared__ float As[GBK][GAS];   // [k][m]
    __shared__ float Bs[GBK][GAS];   // [k][n]

    const int tx = threadIdx.x, ty = threadIdx.y;
    const int tid = ty * 16 + tx;
    const int rowA0 = blockIdx.y * GBM;
    const int rowB0 = blockIdx.x * GBN;

    float c[8][8];
#pragma unroll
    for (int i = 0; i < 8; i++)
#pragma unroll
        for (int j = 0; j < 8; j++) c[i][j] = 0.0f;

    const float* Ap = Aptr + (size_t)rowA0 * K;
    const float* Bp = W    + (size_t)rowB0 * K;

    for (int k0 = 0; k0 < K; k0 += GBK) {
#pragma unroll
        for (int it = 0; it < 2; it++) {
            int l   = it * 256 + tid;
            int row = l >> 2;            // 0..127
            int kq  = (l & 3) * 4;       // 0,4,8,12
            float4 va = *(const float4*)(Ap + (size_t)row * K + k0 + kq);
            As[kq + 0][row] = va.x; As[kq + 1][row] = va.y;
            As[kq + 2][row] = va.z; As[kq + 3][row] = va.w;
            float4 vb = *(const float4*)(Bp + (size_t)row * K + k0 + kq);
            Bs[kq + 0][row] = vb.x; Bs[kq + 1][row] = vb.y;
            Bs[kq + 2][row] = vb.z; Bs[kq + 3][row] = vb.w;
        }
        __syncthreads();
#pragma unroll
        for (int k = 0; k < GBK; k++) {
            float a[8], b[8];
            // Issue all four 128-bit LDS back-to-back (MLP=4) before FFMAs
            *(float4*)(a)     = *(const float4*)&As[k][ty * 8];
            *(float4*)(b)     = *(const float4*)&Bs[k][tx * 8];
            *(float4*)(a + 4) = *(const float4*)&As[k][ty * 8 + 4];
            *(float4*)(b + 4) = *(const float4*)&Bs[k][tx * 8 + 4];
#pragma unroll
            for (int i = 0; i < 8; i++)
#pragma unroll
                for (int j = 0; j < 8; j++)
                    c[i][j] += a[i] * b[j];
        }
        __syncthreads();
    }

    // Epilogue
#pragma unroll
    for (int i = 0; i < 8; i++) {
        int m = rowA0 + ty * 8 + i;
        if (MODE == 0) {
            int b = m >> 11;       // / 2048
            int t = m & 2047;
#pragma unroll
            for (int j4 = 0; j4 < 8; j4 += 4) {
                int n = rowB0 + tx * 8 + j4;
                int h = n >> 7;    // / 128
                int d = n & 127;
                float4 v = make_float4(c[i][j4], c[i][j4 + 1], c[i][j4 + 2], c[i][j4 + 3]);
                *(float4*)&outq[(((size_t)(b * NH + h)) * TT + t) * HD + d] = v;
            }
        } else {
#pragma unroll
            for (int j4 = 0; j4 < 8; j4 += 4) {
                int n = rowB0 + tx * 8 + j4;
                float4 v = make_float4(c[i][j4], c[i][j4 + 1], c[i][j4 + 2], c[i][j4 + 3]);
                *(float4*)&Oplain[(size_t)m * CC + n] = v;
            }
        }
    }
}

// ---------------------------------------------------------------------------
// Flash-attention (non-causal), fp32. 64 queries x 64 keys per tile, D=128.
// 256 threads (16x16). Thread (tx,ty): S microtile rows ty*4+i, cols tx*4+j;
// O accumulator rows ty*4+i, cols {tx*4+j, 64+tx*4+j}.
// Row-group = 16 consecutive lanes (same ty) -> shfl width-16 reductions.
// ---------------------------------------------------------------------------
#define TQ 64
#define TK 64
#define TRS 68    // transposed-tile stride ([d][row])
#define VSS 132   // V natural-tile stride  ([s][d])
#define PSS 68    // P tile stride          ([r][s])
#define ATTN_SMEM_FLOATS (128 * TRS + 128 * TRS + 64 * PSS)
#define ATTN_SMEM_BYTES  (ATTN_SMEM_FLOATS * 4)   // 87040

__global__ __launch_bounds__(256)
void attn_kernel()
{
    extern __shared__ float sm[];
    float* QsT = sm;                    // [128][TRS] : Q^T, pre-scaled
    float* KVb = sm + 128 * TRS;        // K^T [128][TRS]  OR  V [64][VSS]
    float* Ps  = KVb + 128 * TRS;       // [64][PSS]

    const int tx = threadIdx.x, ty = threadIdx.y;
    const int tid = ty * 16 + tx;
    const int bh = blockIdx.y;          // b*NH + h
    const int q0 = blockIdx.x * TQ;
    const float scale = 0.08838834764831845f;   // 1/sqrt(128)

    const float* Qg = g_q + ((size_t)bh * TT + q0) * HD;
    const float* Kg = g_k + (size_t)bh * TT * HD;
    const float* Vg = g_v + (size_t)bh * TT * HD;

    // Load Q tile transposed + pre-scaled
#pragma unroll
    for (int it = 0; it < 8; it++) {
        int f4  = (tid & 3) + it * 4;   // 0..31
        int row = tid >> 2;             // 0..63
        int d   = f4 * 4;
        float4 v = *(const float4*)(Qg + (size_t)row * HD + d);
        QsT[(d + 0) * TRS + row] = v.x * scale;
        QsT[(d + 1) * TRS + row] = v.y * scale;
        QsT[(d + 2) * TRS + row] = v.z * scale;
        QsT[(d + 3) * TRS + row] = v.w * scale;
    }

    float m_i[4], l_i[4], acc[4][8];
#pragma unroll
    for (int i = 0; i < 4; i++) {
        m_i[i] = -1e30f;
        l_i[i] = 0.0f;
#pragma unroll
        for (int j = 0; j < 8; j++) acc[i][j] = 0.0f;
    }

    for (int s0 = 0; s0 < TT; s0 += TK) {
        __syncthreads();   // prior V reads done (and Q stores visible, 1st iter)

        // Load K tile transposed into KVb
#pragma unroll
        for (int it = 0; it < 8; it++) {
            int f4  = (tid & 3) + it * 4;
            int row = tid >> 2;
            int d   = f4 * 4;
            float4 v = *(const float4*)(Kg + (size_t)(s0 + row) * HD + d);
            KVb[(d + 0) * TRS + row] = v.x;
            KVb[(d + 1) * TRS + row] = v.y;
            KVb[(d + 2) * TRS + row] = v.z;
            KVb[(d + 3) * TRS + row] = v.w;
        }
        __syncthreads();

        // S = (Q*scale) K^T  (4x4 per thread)
        float s[4][4];
#pragma unroll
        for (int i = 0; i < 4; i++)
#pragma unroll
            for (int j = 0; j < 4; j++) s[i][j] = 0.0f;

#pragma unroll 4
        for (int k = 0; k < HD; k++) {
            float a[4], b[4];
            *(float4*)a = *(const float4*)&QsT[k * TRS + ty * 4];
            *(float4*)b = *(const float4*)&KVb[k * TRS + tx * 4];
#pragma unroll
            for (int i = 0; i < 4; i++)
#pragma unroll
                for (int j = 0; j < 4; j++)
                    s[i][j] += a[i] * b[j];
        }

        // Online softmax per row, write P tile
#pragma unroll
        for (int i = 0; i < 4; i++) {
            float mx = fmaxf(fmaxf(s[i][0], s[i][1]), fmaxf(s[i][2], s[i][3]));
#pragma unroll
            for (int off = 1; off < 16; off <<= 1)
                mx = fmaxf(mx, __shfl_xor_sync(0xffffffffu, mx, off, 16));
            float mnew = fmaxf(m_i[i], mx);
            float corr = __expf(m_i[i] - mnew);
            float rs = 0.0f;
#pragma unroll
            for (int j = 0; j < 4; j++) {
                float p = __expf(s[i][j] - mnew);
                s[i][j] = p;
                rs += p;
            }
#pragma unroll
            for (int off = 1; off < 16; off <<= 1)
                rs += __shfl_xor_sync(0xffffffffu, rs, off, 16);
            l_i[i] = l_i[i] * corr + rs;
            m_i[i] = mnew;
#pragma unroll
            for (int j = 0; j < 8; j++) acc[i][j] *= corr;
            *(float4*)&Ps[(ty * 4 + i) * PSS + tx * 4] =
                make_float4(s[i][0], s[i][1], s[i][2], s[i][3]);
        }
        __syncthreads();   // Ps complete; K-tile reads complete

        // Load V tile (natural layout) into KVb
#pragma unroll
        for (int it = 0; it < 8; it++) {
            int l   = it * 256 + tid;
            int row = l >> 5;           // 0..63
            int f4  = l & 31;
            *(float4*)&KVb[row * VSS + f4 * 4] =
                *(const float4*)(Vg + (size_t)(s0 + row) * HD + f4 * 4);
        }
        __syncthreads();

        // acc += P @ V
        for (int s4 = 0; s4 < TK; s4 += 4) {
            float p[4][4];
#pragma unroll
            for (int i = 0; i < 4; i++)
                *(float4*)p[i] = *(const float4*)&Ps[(ty * 4 + i) * PSS + s4];
#pragma unroll
            for (int ss = 0; ss < 4; ss++) {
                float4 v0 = *(const float4*)&KVb[(s4 + ss) * VSS + tx * 4];
                float4 v1 = *(const float4*)&KVb[(s4 + ss) * VSS + 64 + tx * 4];
#pragma unroll
                for (int i = 0; i < 4; i++) {
                    float pv = p[i][ss];
                    acc[i][0] += pv * v0.x; acc[i][1] += pv * v0.y;
                    acc[i][2] += pv * v0.z; acc[i][3] += pv * v0.w;
                    acc[i][4] += pv * v1.x; acc[i][5] += pv * v1.y;
                    acc[i][6] += pv * v1.z; acc[i][7] += pv * v1.w;
                }
            }
        }
    }

    // Normalize and write to g_y in [B,T,C] layout
    const int b = bh >> 4;   // / NH
    const int h = bh & 15;
#pragma unroll
    for (int i = 0; i < 4; i++) {
        float inv = 1.0f / l_i[i];
        int t = q0 + ty * 4 + i;
        float* yp = g_y + ((size_t)(b * TT + t)) * CC + h * HD;
        *(float4*)(yp + tx * 4) =
            make_float4(acc[i][0] * inv, acc[i][1] * inv, acc[i][2] * inv, acc[i][3] * inv);
        *(float4*)(yp + 64 + tx * 4) =
            make_float4(acc[i][4] * inv, acc[i][5] * inv, acc[i][6] * inv, acc[i][7] * inv);
    }
}

// ---------------------------------------------------------------------------
// Launch
// ---------------------------------------------------------------------------
extern "C" void kernel_launch(void* const* d_in, const int* in_sizes, int n_in,
                              void* d_out, int out_size)
{
    const float* x  = (const float*)d_in[0];
    const float* wq = (const float*)d_in[1];
    const float* wk = (const float*)d_in[2];
    const float* wv = (const float*)d_in[3];
    const float* wo = (const float*)d_in[4];
    float* out = (float*)d_out;

    cudaFuncSetAttribute(attn_kernel,
                         cudaFuncAttributeMaxDynamicSharedMemorySize,
                         ATTN_SMEM_BYTES);

    dim3 blk(16, 16);

    // Q/K/V projections (permuted epilogue into [B,H,T,D])
    sgemm_nt<0><<<dim3(CC / GBN, MTOT / GBM, 3), blk>>>(x, wq, wk, wv, nullptr);

    // Attention -> g_y [B,T,C]
    attn_kernel<<<dim3(TT / TQ, BD * NH), blk, ATTN_SMEM_BYTES>>>();

    // Output projection -> d_out
    sgemm_nt<1><<<dim3(CC / GBN, MTOT / GBM, 1), blk>>>(nullptr, wo, nullptr, nullptr, out);
}